// round 3
// baseline (speedup 1.0000x reference)
#include <cuda_runtime.h>
#include <cuda_bf16.h>
#include <cstdint>

// Problem constants (fixed by setup_inputs)
#define BATCH   16
#define IMG_H   192
#define IMG_W   640
#define HW      (IMG_H * IMG_W)       // 122880
#define XS      240                   // W*3/8
#define XE      400                   // W*5/8
#define PRIOR_W (XE - XS)             // 160
#define NPRIOR  15360                 // (192-96)*160
#define ITERS   200
#define KMED    ((NPRIOR - 1) / 2)    // 7679, torch lower-median index

// Scratch (static device globals — no allocation)
__device__ float4   g_prior[BATCH * NPRIOR];    // packed prior points (x,y,z,0)
__device__ float    g_prior_y[BATCH * NPRIOR];  // y channel contiguous (for median)
__device__ float    g_thr[BATCH];
__device__ unsigned g_best[BATCH];              // (count<<8) | (199-iter)
__device__ float    g_plane[BATCH * 4];

// ---------------------------------------------------------------------------
// order-preserving float <-> uint key
// ---------------------------------------------------------------------------
__device__ __forceinline__ unsigned fkey(float f) {
    unsigned u = __float_as_uint(f);
    return (u & 0x80000000u) ? ~u : (u | 0x80000000u);
}
__device__ __forceinline__ float kfloat(unsigned k) {
    unsigned u = (k & 0x80000000u) ? (k ^ 0x80000000u) : ~k;
    return __uint_as_float(u);
}

// ---------------------------------------------------------------------------
// Kernel 1: pack prior crop into contiguous buffers; init g_best
// ---------------------------------------------------------------------------
__global__ void pack_kernel(const float* __restrict__ pt,
                            const float* __restrict__ Kmat) {
    int idx = blockIdx.x * blockDim.x + threadIdx.x;
    if (idx < BATCH) g_best[idx] = 0u;
    if (idx >= BATCH * NPRIOR) return;
    int b = idx / NPRIOR;
    int n = idx - b * NPRIOR;
    int ys = (int)Kmat[b * 9 + 5];            // K[b,1,2] -> 96
    int r = n / PRIOR_W;
    int c = n - r * PRIOR_W;
    long base = (long)b * 3 * HW + (long)(ys + r) * IMG_W + XS + c;
    float x = pt[base];
    float y = pt[base + HW];
    float z = pt[base + 2 * HW];
    g_prior[idx]   = make_float4(x, y, z, 0.0f);
    g_prior_y[idx] = y;
}

// ---------------------------------------------------------------------------
// Kernel 2: exact lower-median via 4-pass radix select, twice:
//   med = median_low(y);  thr = median_low(|med - y|)
// One block per batch.
// ---------------------------------------------------------------------------
__global__ void median_kernel() {
    __shared__ unsigned hist[256];
    __shared__ unsigned s_prefix;
    __shared__ unsigned s_k;
    __shared__ float    s_med;

    const int b   = blockIdx.x;
    const int tid = threadIdx.x;
    const float* __restrict__ yv = &g_prior_y[b * NPRIOR];

    for (int mode = 0; mode < 2; mode++) {
        if (tid == 0) { s_prefix = 0u; s_k = KMED; }
        __syncthreads();
        float med = (mode == 1) ? s_med : 0.0f;

        for (int pass = 0; pass < 4; pass++) {
            const int shift = 24 - 8 * pass;
            for (int i = tid; i < 256; i += blockDim.x) hist[i] = 0u;
            __syncthreads();
            const unsigned pref = s_prefix;
            for (int n = tid; n < NPRIOR; n += blockDim.x) {
                float v = yv[n];
                if (mode) v = fabsf(med - v);
                unsigned key = fkey(v);
                bool ok = (pass == 0) ||
                          ((key >> (shift + 8)) == (pref >> (shift + 8)));
                if (ok) atomicAdd(&hist[(key >> shift) & 255u], 1u);
            }
            __syncthreads();
            if (tid == 0) {
                unsigned cum = 0, kk = s_k;
                for (int bin = 0; bin < 256; bin++) {
                    unsigned h = hist[bin];
                    if (cum + h > kk) {
                        s_prefix = pref | ((unsigned)bin << shift);
                        s_k = kk - cum;
                        break;
                    }
                    cum += h;
                }
            }
            __syncthreads();
        }
        if (tid == 0) {
            float val = kfloat(s_prefix);
            if (mode == 0) s_med = val;
            else           g_thr[b] = val;
        }
        __syncthreads();
    }
}

// ---------------------------------------------------------------------------
// Plane hypothesis (matches jnp.cross / norm / d = -n.p1)
// ---------------------------------------------------------------------------
__device__ __forceinline__ void compute_plane(const float4* __restrict__ prior,
                                              const int* __restrict__ sidx,
                                              int i,
                                              float& nx, float& ny, float& nz,
                                              float& d) {
    int s0 = sidx[i * 3 + 0];
    int s1 = sidx[i * 3 + 1];
    int s2 = sidx[i * 3 + 2];
    float4 p1 = prior[s0];
    float4 p2 = prior[s1];
    float4 p3 = prior[s2];
    float ax = p2.x - p1.x, ay = p2.y - p1.y, az = p2.z - p1.z;
    float bx = p3.x - p1.x, by = p3.y - p1.y, bz = p3.z - p1.z;
    nx = ay * bz - az * by;
    ny = az * bx - ax * bz;
    nz = ax * by - ay * bx;
    float norm = sqrtf(nx * nx + ny * ny + nz * nz);
    float inv = 1.0f / (norm + 1e-8f);
    nx *= inv; ny *= inv; nz *= inv;
    d = -(nx * p1.x + ny * p1.y + nz * p1.z);
}

// ---------------------------------------------------------------------------
// Kernel 3: RANSAC inlier counting. One warp per (batch, hypothesis).
// grid = (25, 16), block = 256 (8 warps -> 8 hypotheses per block)
// ---------------------------------------------------------------------------
__global__ void ransac_kernel(const int* __restrict__ sidx) {
    const int b    = blockIdx.y;
    const int warp = threadIdx.x >> 5;
    const int lane = threadIdx.x & 31;
    const int i    = blockIdx.x * 8 + warp;
    if (i >= ITERS) return;

    const float4* __restrict__ prior = &g_prior[b * NPRIOR];
    float nx, ny, nz, d;
    compute_plane(prior, sidx, i, nx, ny, nz, d);
    const float thr = g_thr[b];

    int count = 0;
    #pragma unroll 4
    for (int n = lane; n < NPRIOR; n += 32) {
        float4 p = prior[n];
        float dist = fabsf(nx * p.x + ny * p.y + nz * p.z + d);
        count += (dist <= thr) ? 1 : 0;
    }
    count = __reduce_add_sync(0xFFFFFFFFu, count);
    if (lane == 0) {
        // argmax with first-index tie-break: larger count wins;
        // equal count -> larger (199-i) wins -> smaller i wins.
        unsigned key = ((unsigned)count << 8) | (unsigned)(ITERS - 1 - i);
        atomicMax(&g_best[b], key);
    }
}

// ---------------------------------------------------------------------------
// Kernel 4: recompute winning plane, write to output head + g_plane
// ---------------------------------------------------------------------------
__global__ void finalize_kernel(const int* __restrict__ sidx,
                                float* __restrict__ out) {
    int b = threadIdx.x;
    if (b >= BATCH) return;
    unsigned best = g_best[b];
    int i = ITERS - 1 - (int)(best & 0xFFu);
    float nx, ny, nz, d;
    compute_plane(&g_prior[b * NPRIOR], sidx, i, nx, ny, nz, d);
    g_plane[b * 4 + 0] = nx;
    g_plane[b * 4 + 1] = ny;
    g_plane[b * 4 + 2] = nz;
    g_plane[b * 4 + 3] = d;
    out[b * 4 + 0] = nx;
    out[b * 4 + 1] = ny;
    out[b * 4 + 2] = nz;
    out[b * 4 + 3] = d;
}

// ---------------------------------------------------------------------------
// Kernel 5: full-image inlier mask (0.0 / 1.0), written after planes
// ---------------------------------------------------------------------------
__global__ void mask_kernel(const float* __restrict__ pt,
                            float* __restrict__ out) {
    int idx = blockIdx.x * blockDim.x + threadIdx.x;
    if (idx >= BATCH * HW) return;
    int b = idx / HW;
    int m = idx - b * HW;
    float nx  = g_plane[b * 4 + 0];
    float ny  = g_plane[b * 4 + 1];
    float nz  = g_plane[b * 4 + 2];
    float d   = g_plane[b * 4 + 3];
    float thr = g_thr[b];
    long base = (long)b * 3 * HW + m;
    float dist = fabsf(nx * pt[base] + ny * pt[base + HW] +
                       nz * pt[base + 2 * HW] + d);
    out[BATCH * 4 + idx] = (dist <= thr) ? 1.0f : 0.0f;
}

// ---------------------------------------------------------------------------
extern "C" void kernel_launch(void* const* d_in, const int* in_sizes, int n_in,
                              void* d_out, int out_size) {
    const float* pt   = (const float*)d_in[0];   // (B, 3, H*W)
    const float* Kmat = (const float*)d_in[1];   // (B, 3, 3)
    const int*   sidx = (const int*)d_in[2];     // (200, 3)
    float*       out  = (float*)d_out;           // [B*4 planes][B*H*W mask]

    {
        int total = BATCH * NPRIOR;
        pack_kernel<<<(total + 255) / 256, 256>>>(pt, Kmat);
    }
    median_kernel<<<BATCH, 1024>>>();
    {
        dim3 grid(25, BATCH);
        ransac_kernel<<<grid, 256>>>(sidx);
    }
    finalize_kernel<<<1, 32>>>(sidx, out);
    {
        int total = BATCH * HW;
        mask_kernel<<<(total + 255) / 256, 256>>>(pt, out);
    }
}

// round 5
// speedup vs baseline: 2.1236x; 2.1236x over previous
#include <cuda_runtime.h>
#include <cuda_bf16.h>
#include <cstdint>

// Problem constants (fixed by setup_inputs)
#define BATCH   16
#define IMG_H   192
#define IMG_W   640
#define HW      (IMG_H * IMG_W)       // 122880
#define XS      240                   // W*3/8
#define XE      400                   // W*5/8
#define PRIOR_W (XE - XS)             // 160
#define NPRIOR  15360                 // (192-96)*160
#define ITERS   200
#define KMED    ((NPRIOR - 1) / 2)    // 7679, torch lower-median index
#define NH      8                     // hypotheses per ransac block

// Scratch (static device globals — no allocation)
__device__ float4   g_prior[BATCH * NPRIOR];    // packed prior points (x,y,z,0)
__device__ float    g_prior_y[BATCH * NPRIOR];  // y channel contiguous (median)
__device__ float    g_thr[BATCH];
__device__ unsigned g_best[BATCH];              // (count<<8) | (199-iter)

// ---------------------------------------------------------------------------
// order-preserving float <-> uint key
// ---------------------------------------------------------------------------
__device__ __forceinline__ unsigned fkey(float f) {
    unsigned u = __float_as_uint(f);
    return (u & 0x80000000u) ? ~u : (u | 0x80000000u);
}
__device__ __forceinline__ float kfloat(unsigned k) {
    unsigned u = (k & 0x80000000u) ? (k ^ 0x80000000u) : ~k;
    return __uint_as_float(u);
}

// ---------------------------------------------------------------------------
// Kernel 1: pack prior crop into contiguous buffers; init g_best
// ---------------------------------------------------------------------------
__global__ void pack_kernel(const float* __restrict__ pt,
                            const float* __restrict__ Kmat) {
    int idx = blockIdx.x * blockDim.x + threadIdx.x;
    if (idx < BATCH) g_best[idx] = 0u;
    if (idx >= BATCH * NPRIOR) return;
    int b = idx / NPRIOR;
    int n = idx - b * NPRIOR;
    int ys = (int)Kmat[b * 9 + 5];            // K[b,1,2] -> 96
    int r = n / PRIOR_W;
    int c = n - r * PRIOR_W;
    long base = (long)b * 3 * HW + (long)(ys + r) * IMG_W + XS + c;
    float x = pt[base];
    float y = pt[base + HW];
    float z = pt[base + 2 * HW];
    g_prior[idx]   = make_float4(x, y, z, 0.0f);
    g_prior_y[idx] = y;
}

// ---------------------------------------------------------------------------
// Kernel 2: exact lower-median via 3-pass (11/11/10-bit) radix select, twice:
//   med = median_low(y);  thr = median_low(|med - y|)
// One block per batch, 1024 threads. y cached in shared; bin selection via
// parallel block scan. Digit layout: bits [21:32), [10:21), [0:10).
// Pass filter compares all bits >= HI[pass] of the resolved prefix.
// ---------------------------------------------------------------------------
__global__ void __launch_bounds__(1024) median_kernel() {
    __shared__ float    s_y[NPRIOR];       // 60 KB
    __shared__ unsigned s_hist[2048];      // 8 KB
    __shared__ unsigned s_wsum[32];
    __shared__ unsigned s_woff[32];
    __shared__ unsigned s_prefix;
    __shared__ unsigned s_k;
    __shared__ float    s_med;

    const int b    = blockIdx.x;
    const int tid  = threadIdx.x;
    const int lane = tid & 31;
    const int w    = tid >> 5;

    // load y into shared once
    const float* __restrict__ yv = &g_prior_y[b * NPRIOR];
    #pragma unroll
    for (int n = tid; n < NPRIOR; n += 1024) s_y[n] = yv[n];
    __syncthreads();

    const int SHIFT[3]      = {21, 10, 0};     // digit start bit
    const unsigned DMASK[3] = {0x7FFu, 0x7FFu, 0x3FFu};
    const int HI[3]         = {32, 21, 10};    // resolved-prefix boundary

    for (int mode = 0; mode < 2; mode++) {
        if (tid == 0) { s_prefix = 0u; s_k = KMED; }
        __syncthreads();
        const float med = (mode == 1) ? s_med : 0.0f;

        for (int pass = 0; pass < 3; pass++) {
            const int shift = SHIFT[pass];
            const unsigned dmask = DMASK[pass];
            const int hi = HI[pass];
            // zero histogram (2 bins per thread)
            s_hist[tid]        = 0u;
            s_hist[tid + 1024] = 0u;
            __syncthreads();
            const unsigned pref = s_prefix;
            const unsigned kk   = s_k;

            // build histogram over elements matching the resolved prefix
            #pragma unroll
            for (int n = tid; n < NPRIOR; n += 1024) {
                float v = s_y[n];
                if (mode) v = fabsf(med - v);
                unsigned key = fkey(v);
                bool ok = (pass == 0) || ((key >> hi) == (pref >> hi));
                if (ok) atomicAdd(&s_hist[(key >> shift) & dmask], 1u);
            }
            __syncthreads();

            // parallel exclusive scan over 2048 bins (2 contiguous per thread)
            unsigned h0 = s_hist[2 * tid];
            unsigned h1 = s_hist[2 * tid + 1];
            unsigned local = h0 + h1;
            unsigned incl = local;
            #pragma unroll
            for (int o = 1; o < 32; o <<= 1) {
                unsigned v = __shfl_up_sync(0xFFFFFFFFu, incl, o);
                if (lane >= o) incl += v;
            }
            if (lane == 31) s_wsum[w] = incl;
            __syncthreads();
            if (w == 0) {
                unsigned v = s_wsum[lane];
                unsigned s = v;
                #pragma unroll
                for (int o = 1; o < 32; o <<= 1) {
                    unsigned t = __shfl_up_sync(0xFFFFFFFFu, s, o);
                    if (lane >= o) s += t;
                }
                s_woff[lane] = s - v;   // exclusive warp offset
            }
            __syncthreads();
            unsigned excl = s_woff[w] + (incl - local);
            unsigned cum0 = excl;
            unsigned cum1 = excl + h0;
            if (kk >= cum0 && kk < cum0 + h0) {
                s_prefix = pref | ((unsigned)(2 * tid) << shift);
                s_k = kk - cum0;
            }
            if (kk >= cum1 && kk < cum1 + h1) {
                s_prefix = pref | ((unsigned)(2 * tid + 1) << shift);
                s_k = kk - cum1;
            }
            __syncthreads();
        }
        if (tid == 0) {
            float val = kfloat(s_prefix);
            if (mode == 0) s_med = val;
            else           g_thr[b] = val;
        }
        __syncthreads();
    }
}

// ---------------------------------------------------------------------------
// Plane hypothesis (matches jnp.cross / norm / d = -n.p1)
// ---------------------------------------------------------------------------
__device__ __forceinline__ float4 compute_plane(const float4* __restrict__ prior,
                                                const int* __restrict__ sidx,
                                                int i) {
    int s0 = sidx[i * 3 + 0];
    int s1 = sidx[i * 3 + 1];
    int s2 = sidx[i * 3 + 2];
    float4 p1 = prior[s0];
    float4 p2 = prior[s1];
    float4 p3 = prior[s2];
    float ax = p2.x - p1.x, ay = p2.y - p1.y, az = p2.z - p1.z;
    float bx = p3.x - p1.x, by = p3.y - p1.y, bz = p3.z - p1.z;
    float nx = ay * bz - az * by;
    float ny = az * bx - ax * bz;
    float nz = ax * by - ay * bx;
    float norm = sqrtf(nx * nx + ny * ny + nz * nz);
    float inv = 1.0f / (norm + 1e-8f);
    nx *= inv; ny *= inv; nz *= inv;
    float d = -(nx * p1.x + ny * p1.y + nz * p1.z);
    return make_float4(nx, ny, nz, d);
}

// ---------------------------------------------------------------------------
// Kernel 3: RANSAC inlier counting. One block = NH(8) hypotheses, single
// shared streaming pass over the points (loop interchange: 8x fewer loads).
// grid = (25, 16), block = 256
// ---------------------------------------------------------------------------
__global__ void __launch_bounds__(256) ransac_kernel(const int* __restrict__ sidx) {
    __shared__ float4 s_plane[NH];
    __shared__ unsigned s_cnt[NH];

    const int b   = blockIdx.y;
    const int tid = threadIdx.x;
    const int i0  = blockIdx.x * NH;

    const float4* __restrict__ prior = &g_prior[b * NPRIOR];

    if (tid < NH) {
        s_plane[tid] = compute_plane(prior, sidx, i0 + tid);
        s_cnt[tid] = 0u;
    }
    __syncthreads();

    const float thr = g_thr[b];
    float4 pl[NH];
    #pragma unroll
    for (int h = 0; h < NH; h++) pl[h] = s_plane[h];

    int cnt[NH];
    #pragma unroll
    for (int h = 0; h < NH; h++) cnt[h] = 0;

    #pragma unroll 2
    for (int n = tid; n < NPRIOR; n += 256) {
        float4 p = prior[n];
        #pragma unroll
        for (int h = 0; h < NH; h++) {
            float dist = fabsf(fmaf(pl[h].x, p.x,
                               fmaf(pl[h].y, p.y,
                               fmaf(pl[h].z, p.z, pl[h].w))));
            cnt[h] += (dist <= thr) ? 1 : 0;
        }
    }

    #pragma unroll
    for (int h = 0; h < NH; h++) {
        int c = __reduce_add_sync(0xFFFFFFFFu, cnt[h]);
        if ((tid & 31) == 0) atomicAdd(&s_cnt[h], (unsigned)c);
    }
    __syncthreads();

    if (tid < NH) {
        int i = i0 + tid;
        // argmax with first-index tie-break: larger count wins;
        // equal count -> larger (199-i) wins -> smaller i wins.
        unsigned key = (s_cnt[tid] << 8) | (unsigned)(ITERS - 1 - i);
        atomicMax(&g_best[b], key);
    }
}

// ---------------------------------------------------------------------------
// Kernel 4: full-image inlier mask (0.0/1.0), float4 vectorized, with the
// winning plane recomputed per block (finalize fused). Block = 256 threads
// covering 1024 consecutive pixels; 120 blocks per batch.
// ---------------------------------------------------------------------------
__global__ void __launch_bounds__(256) mask_kernel(const float* __restrict__ pt,
                                                   const int* __restrict__ sidx,
                                                   float* __restrict__ out) {
    __shared__ float4 s_pl;
    __shared__ float  s_thr;

    const int tid  = threadIdx.x;
    const int blk  = blockIdx.x;
    const int b    = blk / (HW / 1024);          // 120 blocks per batch
    const int mblk = (blk - b * (HW / 1024)) * 1024;

    if (tid == 0) {
        unsigned best = g_best[b];
        int i = ITERS - 1 - (int)(best & 0xFFu);
        float4 pl = compute_plane(&g_prior[b * NPRIOR], sidx, i);
        s_pl  = pl;
        s_thr = g_thr[b];
        if (mblk == 0) {                          // write plane head once per batch
            out[b * 4 + 0] = pl.x;
            out[b * 4 + 1] = pl.y;
            out[b * 4 + 2] = pl.z;
            out[b * 4 + 3] = pl.w;
        }
    }
    __syncthreads();

    const float4 pl  = s_pl;
    const float  thr = s_thr;
    const int m = mblk + tid * 4;                 // 4 pixels per thread
    const long base = (long)b * 3 * HW + m;

    float4 x4 = *(const float4*)(pt + base);
    float4 y4 = *(const float4*)(pt + base + HW);
    float4 z4 = *(const float4*)(pt + base + 2 * HW);

    float4 r;
    r.x = (fabsf(fmaf(pl.x, x4.x, fmaf(pl.y, y4.x, fmaf(pl.z, z4.x, pl.w)))) <= thr) ? 1.0f : 0.0f;
    r.y = (fabsf(fmaf(pl.x, x4.y, fmaf(pl.y, y4.y, fmaf(pl.z, z4.y, pl.w)))) <= thr) ? 1.0f : 0.0f;
    r.z = (fabsf(fmaf(pl.x, x4.z, fmaf(pl.y, y4.z, fmaf(pl.z, z4.z, pl.w)))) <= thr) ? 1.0f : 0.0f;
    r.w = (fabsf(fmaf(pl.x, x4.w, fmaf(pl.y, y4.w, fmaf(pl.z, z4.w, pl.w)))) <= thr) ? 1.0f : 0.0f;

    *(float4*)(out + BATCH * 4 + (long)b * HW + m) = r;
}

// ---------------------------------------------------------------------------
extern "C" void kernel_launch(void* const* d_in, const int* in_sizes, int n_in,
                              void* d_out, int out_size) {
    const float* pt   = (const float*)d_in[0];   // (B, 3, H*W)
    const float* Kmat = (const float*)d_in[1];   // (B, 3, 3)
    const int*   sidx = (const int*)d_in[2];     // (200, 3)
    float*       out  = (float*)d_out;           // [B*4 planes][B*H*W mask]

    {
        int total = BATCH * NPRIOR;
        pack_kernel<<<(total + 255) / 256, 256>>>(pt, Kmat);
    }
    median_kernel<<<BATCH, 1024>>>();
    {
        dim3 grid(ITERS / NH, BATCH);            // (25, 16)
        ransac_kernel<<<grid, 256>>>(sidx);
    }
    {
        int blocks = BATCH * HW / 1024;          // 1920
        mask_kernel<<<blocks, 256>>>(pt, sidx, out);
    }
}